// round 15
// baseline (speedup 1.0000x reference)
#include <cuda_runtime.h>
#include <math.h>

// ---------------------------------------------------------------------------
// RelativePositionalEncoding, fully fused single kernel:
// out[b,s,d] = nodes[b,s,d] + (s <= n_b) ? pe[(s - n_b) mod 5000, d] : 0
// pe[p,2j] = sin(p*div_j), pe[p,2j+1] = cos(p*div_j), div_j = 10000^(-2j/256)
// B=32, S=4096, D=256.  Trig inline (MUFU), hidden under the DRAM stream.
//
// VPT=4 / 256 threads: best measured occupancy (78.7%) x MLP product.
// Base-pointer + immediate-offset addressing keeps regs ~28.
// ---------------------------------------------------------------------------

#define MAX_LEN 5000
#define B_DIM   32
#define S_DIM   4096
#define D_DIM   256
#define D4      (D_DIM / 4)          // 64 float4 per row
#define VPT     4                    // float4 per thread
#define TPB     256

// Cody-Waite 2-term range reduction to [-pi,pi] + MUFU sin/cos.
__device__ __forceinline__ void fast_sincos(float ang, float* s, float* c) {
    const float INV_2PI   = 0.15915493667125702f;      // 1/(2*pi)
    const float TWO_PI_HI = 6.283185482025146f;        // float(2*pi)
    const float TWO_PI_LO = -1.7484556000744947e-07f;  // 2*pi - TWO_PI_HI
    float k = rintf(ang * INV_2PI);
    float r = fmaf(-k, TWO_PI_HI, ang);
    r = fmaf(-k, TWO_PI_LO, r);
    *s = __sinf(r);
    *c = __cosf(r);
}

__global__ void __launch_bounds__(TPB)
rpe_fused_kernel(const float4* __restrict__ nodes,
                 const int*    __restrict__ num_nodes,
                 float4*       __restrict__ out) {
    // Block covers TPB*VPT = 1024 consecutive float4 = 16 consecutive rows.
    // 1024 divides 262144 (float4 per b): no b/s wrap within a block.
    unsigned base = blockIdx.x * (TPB * VPT) + threadIdx.x;

    unsigned b  = base >> 18;                  // block-uniform
    unsigned d4 = base & (D4 - 1);             // invariant across k (stride 256)
    int      s0 = (int)((base >> 6) & (S_DIM - 1));
    int n = __ldg(&num_nodes[b]);

    // div_j = 2^(2j * -log2(10000)/256); float4 covers pairs j0=2*d4, j1=2*d4+1
    const float c2 = -13.287712379549449f / 256.0f;
    float div0 = exp2f((float)(4 * d4)     * c2);
    float div1 = exp2f((float)(4 * d4 + 2) * c2);

    const float4* src = nodes + base;
    float4*       dst = out   + base;

    // Front-batched streaming loads (immediate offsets -> LDG.E.128 [R+imm]).
    float4 v[VPT];
    #pragma unroll
    for (int k = 0; k < VPT; k++)
        v[k] = __ldcs(&src[k * TPB]);

    int p0 = s0 - n;                           // slice k row delta = p0 + 4k
    #pragma unroll
    for (int k = 0; k < VPT; k++) {
        int p = p0 + 4 * k;                    // <= 0 iff masked
        if (p <= 0) {                          // warp-uniform predicate
            p = (p < 0) ? p + MAX_LEN : 0;     // numpy mod semantics
            float fp = (float)p;               // exact (p < 2^13)
            float sa, ca, sb, cb;
            fast_sincos(fp * div0, &sa, &ca);
            fast_sincos(fp * div1, &sb, &cb);
            v[k].x += sa; v[k].y += ca; v[k].z += sb; v[k].w += cb;
        }
    }

    #pragma unroll
    for (int k = 0; k < VPT; k++)
        __stcs(&dst[k * TPB], v[k]);           // evict-first streaming write
}

// ---------------------------------------------------------------------------
// Launch: 8388608 float4 / (256 * 4) = 8192 blocks.
// ---------------------------------------------------------------------------
extern "C" void kernel_launch(void* const* d_in, const int* in_sizes, int n_in,
                              void* d_out, int out_size) {
    const float4* nodes     = (const float4*)d_in[0];
    const int*    num_nodes = (const int*)d_in[1];
    float4*       out       = (float4*)d_out;

    const unsigned total4 = (unsigned)B_DIM * S_DIM * D4;
    int blocks = total4 / (TPB * VPT);
    rpe_fused_kernel<<<blocks, TPB>>>(nodes, num_nodes, out);
}

// round 17
// speedup vs baseline: 1.0007x; 1.0007x over previous
#include <cuda_runtime.h>
#include <math.h>

// ---------------------------------------------------------------------------
// RelativePositionalEncoding, fully fused single kernel:
// out[b,s,d] = nodes[b,s,d] + (s <= n_b) ? pe[(s - n_b) mod 5000, d] : 0
// pe[p,2j] = sin(p*div_j), pe[p,2j+1] = cos(p*div_j), div_j = 10000^(-2j/256)
// B=32, S=4096, D=256.  Trig inline (MUFU), hidden under the DRAM stream.
//
// VPT=4 / 256 threads: best measured occupancy (78.7%) x MLP product.
// Base-pointer + immediate-offset addressing keeps regs ~28.
// ---------------------------------------------------------------------------

#define MAX_LEN 5000
#define B_DIM   32
#define S_DIM   4096
#define D_DIM   256
#define D4      (D_DIM / 4)          // 64 float4 per row
#define VPT     4                    // float4 per thread
#define TPB     256

// Cody-Waite 2-term range reduction to [-pi,pi] + MUFU sin/cos.
__device__ __forceinline__ void fast_sincos(float ang, float* s, float* c) {
    const float INV_2PI   = 0.15915493667125702f;      // 1/(2*pi)
    const float TWO_PI_HI = 6.283185482025146f;        // float(2*pi)
    const float TWO_PI_LO = -1.7484556000744947e-07f;  // 2*pi - TWO_PI_HI
    float k = rintf(ang * INV_2PI);
    float r = fmaf(-k, TWO_PI_HI, ang);
    r = fmaf(-k, TWO_PI_LO, r);
    *s = __sinf(r);
    *c = __cosf(r);
}

__global__ void __launch_bounds__(TPB)
rpe_fused_kernel(const float4* __restrict__ nodes,
                 const int*    __restrict__ num_nodes,
                 float4*       __restrict__ out) {
    // Block covers TPB*VPT = 1024 consecutive float4 = 16 consecutive rows.
    // 1024 divides 262144 (float4 per b): no b/s wrap within a block.
    unsigned base = blockIdx.x * (TPB * VPT) + threadIdx.x;

    unsigned b  = base >> 18;                  // block-uniform
    unsigned d4 = base & (D4 - 1);             // invariant across k (stride 256)
    int      s0 = (int)((base >> 6) & (S_DIM - 1));
    int n = __ldg(&num_nodes[b]);

    // div_j = 2^(2j * -log2(10000)/256); float4 covers pairs j0=2*d4, j1=2*d4+1
    const float c2 = -13.287712379549449f / 256.0f;
    float div0 = exp2f((float)(4 * d4)     * c2);
    float div1 = exp2f((float)(4 * d4 + 2) * c2);

    const float4* src = nodes + base;
    float4*       dst = out   + base;

    // Front-batched streaming loads (immediate offsets -> LDG.E.128 [R+imm]).
    float4 v[VPT];
    #pragma unroll
    for (int k = 0; k < VPT; k++)
        v[k] = __ldcs(&src[k * TPB]);

    int p0 = s0 - n;                           // slice k row delta = p0 + 4k
    #pragma unroll
    for (int k = 0; k < VPT; k++) {
        int p = p0 + 4 * k;                    // <= 0 iff masked
        if (p <= 0) {                          // warp-uniform predicate
            p = (p < 0) ? p + MAX_LEN : 0;     // numpy mod semantics
            float fp = (float)p;               // exact (p < 2^13)
            float sa, ca, sb, cb;
            fast_sincos(fp * div0, &sa, &ca);
            fast_sincos(fp * div1, &sb, &cb);
            v[k].x += sa; v[k].y += ca; v[k].z += sb; v[k].w += cb;
        }
    }

    #pragma unroll
    for (int k = 0; k < VPT; k++)
        __stcs(&dst[k * TPB], v[k]);           // evict-first streaming write
}

// ---------------------------------------------------------------------------
// Launch: 8388608 float4 / (256 * 4) = 8192 blocks.
// ---------------------------------------------------------------------------
extern "C" void kernel_launch(void* const* d_in, const int* in_sizes, int n_in,
                              void* d_out, int out_size) {
    const float4* nodes     = (const float4*)d_in[0];
    const int*    num_nodes = (const int*)d_in[1];
    float4*       out       = (float4*)d_out;

    const unsigned total4 = (unsigned)B_DIM * S_DIM * D4;
    int blocks = total4 / (TPB * VPT);
    rpe_fused_kernel<<<blocks, TPB>>>(nodes, num_nodes, out);
}